// round 9
// baseline (speedup 1.0000x reference)
#include <cuda_runtime.h>
#include <cuda_bf16.h>
#include <cstdint>

// -------- problem constants --------
#define BB      512
#define TT      256
#define D_IN    64
#define D_STATE 64
#define NN      2048
#define D_OUT   10
#define KAUG    128

// -------- decomposition: 16 neuron-groups x 8 batch-groups = 128 CTAs ----
#define NG      16
#define BG      8
#define NT      128     // neurons per CTA (GEMM1 N, GEMM2 K)
#define BT      64      // batch rows per CTA (M)
#define NCTAS   128
#define THREADS 512

// -------- SMEM: interleaved hi/lo bf16 pairs, 32-bit-word addressed -------
// word[row*RSW + 2*p + 0] = hi bf16x2 of pair p, word[... + 1] = lo bf16x2
#define RSW     136
#define XA_OFF  0
#define E_OFF   (XA_OFF + BT * RSW)
#define SD_OFF  (E_OFF  + NT * RSW)
#define A2_OFF  (SD_OFF + D_STATE * RSW)
#define SMEM_WORDS (A2_OFF + BT * RSW)
#define SMEM_BYTES (SMEM_WORDS * 4)

// -------- global scratch (static; no allocation) --------
__device__ float g_partials[NG][BB][D_STATE];
__device__ float g_ypart[NG][BB][D_OUT];

// per-bi barriers (padded); gen monotonic across graph replays
__device__ unsigned g_cntb[BG * 32];
__device__ volatile unsigned g_genb[BG * 32];

__device__ __forceinline__ void gsync_bi(int bi) {
    __syncthreads();
    if (threadIdx.x == 0) {
        __threadfence();
        unsigned gen = g_genb[bi * 32];            // read BEFORE arriving
        unsigned prev = atomicAdd(&g_cntb[bi * 32], 1);
        if (prev == NG - 1) {
            g_cntb[bi * 32] = 0;
            __threadfence();
            g_genb[bi * 32] = gen + 1;
        } else {
            while (g_genb[bi * 32] == gen) { }
            __threadfence();
        }
    }
    __syncthreads();
}

// -------- warp-level bf16 MMA (sm_80+ baseline PTX; no arch-a gating) -----
__device__ __forceinline__ void mma_bf16(float* c, uint32_t a0, uint32_t a1,
                                         uint32_t a2, uint32_t a3,
                                         uint32_t b0, uint32_t b1) {
    asm volatile(
        "mma.sync.aligned.m16n8k16.row.col.f32.bf16.bf16.f32 "
        "{%0,%1,%2,%3}, {%4,%5,%6,%7}, {%8,%9}, {%0,%1,%2,%3};"
        : "+f"(c[0]), "+f"(c[1]), "+f"(c[2]), "+f"(c[3])
        : "r"(a0), "r"(a1), "r"(a2), "r"(a3), "r"(b0), "r"(b1));
}

// 3-pass split GEMM, 16 x (8*NS) warp tile, K=128. Each k-step loads A/B
// hi+lo once (LDS.64 on interleaved pairs), issues passes hh, lh, hl.
template <int NS>
__device__ __forceinline__ void gemm3(const uint32_t* __restrict__ A,
                                      const uint32_t* __restrict__ B,
                                      int m0, int n0, int g, int t4,
                                      float acc[][4]) {
#pragma unroll
    for (int ks = 0; ks < 8; ks++) {
        const int kp0 = ks * 8 + t4;                 // pair index
        const uint32_t* Ar = A + (m0 + g) * RSW;
        uint2 a0 = *(const uint2*)&Ar[2 * kp0];
        uint2 a1 = *(const uint2*)&Ar[8 * RSW + 2 * kp0];
        uint2 a2 = *(const uint2*)&Ar[2 * (kp0 + 4)];
        uint2 a3 = *(const uint2*)&Ar[8 * RSW + 2 * (kp0 + 4)];
#pragma unroll
        for (int ns = 0; ns < NS; ns++) {
            const uint32_t* Bc = B + (n0 + 8 * ns + g) * RSW;
            uint2 b0 = *(const uint2*)&Bc[2 * kp0];
            uint2 b1 = *(const uint2*)&Bc[2 * (kp0 + 4)];
            mma_bf16(acc[ns], a0.x, a1.x, a2.x, a3.x, b0.x, b1.x);  // hi*hi
            mma_bf16(acc[ns], a0.y, a1.y, a2.y, a3.y, b0.x, b1.x);  // lo*hi
            mma_bf16(acc[ns], a0.x, a1.x, a2.x, a3.x, b0.y, b1.y);  // hi*lo
        }
    }
}

// split (x,y) into bf16 hi/lo pairs, store interleaved as one 8B word-pair
__device__ __forceinline__ void split_store(uint32_t* buf, int row, int kp,
                                            float x, float y) {
    __nv_bfloat162 h, l;
    h.x = __float2bfloat16(x);
    h.y = __float2bfloat16(y);
    l.x = __float2bfloat16(x - __bfloat162float(h.x));
    l.y = __float2bfloat16(y - __bfloat162float(h.y));
    uint2 v;
    v.x = *(uint32_t*)&h;
    v.y = *(uint32_t*)&l;
    *(uint2*)&buf[row * RSW + 2 * kp] = v;
}

__global__ void __launch_bounds__(THREADS, 1)
nef_kernel(const float* __restrict__ seq,     // [B][T][D_IN]
           const float* __restrict__ enc,     // [NN][KAUG]
           const float* __restrict__ bias,    // [NN]
           const float* __restrict__ gain,    // [NN]
           const float* __restrict__ sdec,    // [NN][D_STATE]
           const float* __restrict__ dec,     // [NN][D_OUT]
           float* __restrict__ out)           // [B][D_OUT]
{
    extern __shared__ uint32_t smem[];
    uint32_t* XA = smem + XA_OFF;
    uint32_t* E  = smem + E_OFF;
    uint32_t* SD = smem + SD_OFF;
    uint32_t* A2 = smem + A2_OFF;

    const int tid  = threadIdx.x;
    const int wid  = tid >> 5;
    const int lane = tid & 31;
    const int g    = lane >> 2;          // groupID
    const int t4   = lane & 3;           // thread-in-group
    const int ni   = blockIdx.x & (NG - 1);
    const int bi   = blockIdx.x >> 4;
    const int nbase = ni * NT;
    const int bbase = bi * BT;

    // GEMM1 warp tile (16x32): m0a in {0,16,32,48}, n0a in {0,32,64,96}
    const int m0a = 16 * (wid & 3);
    const int n0a = 32 * (wid >> 2);
    // GEMM2 warp tile (16x16): all 16 warps cover 64x64
    const int m0b = 16 * (wid & 3);
    const int d0b = 16 * (wid >> 2);

    // ---- one-time weight staging ----
    for (int i = tid; i < NT * (KAUG / 2); i += THREADS) {
        int n = i >> 6, p = i & 63;
        float2 v = *(const float2*)&enc[(nbase + n) * KAUG + 2 * p];
        split_store(E, n, p, v.x, v.y);
    }
    for (int i = tid; i < D_STATE * (NT / 2); i += THREADS) {
        int d = i >> 6, p = i & 63;
        float x = sdec[(nbase + 2 * p) * D_STATE + d];
        float y = sdec[(nbase + 2 * p + 1) * D_STATE + d];
        split_store(SD, d, p, x, y);
    }
    // per-thread gain/bias for epilogue1 (columns n0a + 8ns + 2t4 (+1))
    float gj[4][2], bj[4][2];
#pragma unroll
    for (int ns = 0; ns < 4; ns++) {
        int n = nbase + n0a + 8 * ns + 2 * t4;
        gj[ns][0] = gain[n];     gj[ns][1] = gain[n + 1];
        bj[ns][0] = bias[n];     bj[ns][1] = bias[n + 1];
    }

    // ---- initial XA = [u(0) | 0] ----
    for (int i = tid; i < BT * (D_IN / 2); i += THREADS) {
        int r = i >> 5, p = i & 31;
        float2 v = *(const float2*)&seq[((size_t)(bbase + r) * TT) * D_IN + 2 * p];
        split_store(XA, r, p, v.x, v.y);
    }
    for (int i = tid; i < BT * (D_STATE / 2); i += THREADS) {
        int r = i >> 5, p = i & 31;
        split_store(XA, r, 32 + p, 0.f, 0.f);
    }
    __syncthreads();

    // prefetch: each thread owns 4 u-pairs -> full 64x32-pair coverage
    int prr[4], ppp[4];
#pragma unroll
    for (int q = 0; q < 4; q++) {
        int item = tid * 4 + q;              // 0..2047
        prr[q] = item >> 5;                  // row 0..63
        ppp[q] = item & 31;                  // pair 0..31
    }

    for (int t = 0; t < TT; t++) {
        // ======== GEMM1: a = XA @ E^T (16 warps, 16x32 tiles) ========
        float acc[4][4];
#pragma unroll
        for (int ns = 0; ns < 4; ns++)
#pragma unroll
            for (int q = 0; q < 4; q++) acc[ns][q] = 0.f;

        gemm3<4>(XA, E, m0a, n0a, g, t4, acc);

        // ======== epilogue 1: act = |gain*v + bias| -> A2 ========
#pragma unroll
        for (int ns = 0; ns < 4; ns++) {
            float v0 = fabsf(fmaf(gj[ns][0], acc[ns][0], bj[ns][0]));
            float v1 = fabsf(fmaf(gj[ns][1], acc[ns][1], bj[ns][1]));
            float v2 = fabsf(fmaf(gj[ns][0], acc[ns][2], bj[ns][0]));
            float v3 = fabsf(fmaf(gj[ns][1], acc[ns][3], bj[ns][1]));
            int r0 = m0a + g;
            int kp = (n0a + 8 * ns) / 2 + t4;
            split_store(A2, r0,     kp, v0, v1);
            split_store(A2, r0 + 8, kp, v2, v3);
        }

        if (t == TT - 1) break;

        __syncthreads();   // A2 visible; XA u-part now dead (all warps done)

        // ---- issue u(t+1) loads into registers (latency rides under GEMM2)
        float2 pf[4];
#pragma unroll
        for (int q = 0; q < 4; q++)
            pf[q] = *(const float2*)&seq[((size_t)(bbase + prr[q]) * TT + t + 1) * D_IN + 2 * ppp[q]];

        // ======== GEMM2: s_part = a @ SD (16 warps, 16x16 tiles) ========
        {
            float acc2[2][4];
#pragma unroll
            for (int ns = 0; ns < 2; ns++)
#pragma unroll
                for (int q = 0; q < 4; q++) acc2[ns][q] = 0.f;

            gemm3<2>(A2, SD, m0b, d0b, g, t4, acc2);

#pragma unroll
            for (int ns = 0; ns < 2; ns++) {
                int r0 = m0b + g;
                int d  = d0b + 8 * ns + 2 * t4;
                *(float2*)&g_partials[ni][bbase + r0][d] =
                    make_float2(acc2[ns][0], acc2[ns][1]);
                *(float2*)&g_partials[ni][bbase + r0 + 8][d] =
                    make_float2(acc2[ns][2], acc2[ns][3]);
            }
        }

        // ---- store prefetched u(t+1) into XA u-part ----
#pragma unroll
        for (int q = 0; q < 4; q++)
            split_store(XA, prr[q], ppp[q], pf[q].x, pf[q].y);

        gsync_bi(bi);   // partials from the 16 ni-sharers of this bi visible

        // ---- fused reduce+fill: s[r][d] = sum_g partials[g][bbase+r][d]
        //      directly into XA s-columns ----
#pragma unroll
        for (int j = 0; j < 2; j++) {
            int item = tid + THREADS * j;        // 0..1023
            int r  = item >> 4;                  // 0..63
            int dq = item & 15;                  // float4 block within d
            float4 s = make_float4(0.f, 0.f, 0.f, 0.f);
#pragma unroll
            for (int gg = 0; gg < NG; gg++) {
                float4 v = *(const float4*)&g_partials[gg][bbase + r][dq * 4];
                s.x += v.x; s.y += v.y; s.z += v.z; s.w += v.w;
            }
            split_store(XA, r, 32 + 2 * dq,     s.x, s.y);
            split_store(XA, r, 32 + 2 * dq + 1, s.z, s.w);
        }
        __syncthreads();
    }

    // ======== final decode: y = a @ dec ========
    __syncthreads();
    for (int idx = tid; idx < BT * D_OUT; idx += THREADS) {
        int b = idx / D_OUT, o = idx - b * D_OUT;
        float s = 0.f;
#pragma unroll 4
        for (int p = 0; p < NT / 2; p++) {
            uint2 w = *(const uint2*)&A2[b * RSW + 2 * p];
            __nv_bfloat162 h = *(__nv_bfloat162*)&w.x;
            __nv_bfloat162 l = *(__nv_bfloat162*)&w.y;
            float a0 = __bfloat162float(h.x) + __bfloat162float(l.x);
            float a1 = __bfloat162float(h.y) + __bfloat162float(l.y);
            s += a0 * dec[(nbase + 2 * p) * D_OUT + o];
            s += a1 * dec[(nbase + 2 * p + 1) * D_OUT + o];
        }
        g_ypart[ni][bbase + b][o] = s;
    }
    gsync_bi(bi);

    if (ni == 0) {
        for (int idx = tid; idx < BT * D_OUT; idx += THREADS) {
            int b = idx / D_OUT, o = idx - b * D_OUT;
            float s = 0.f;
#pragma unroll
            for (int gg = 0; gg < NG; gg++)
                s += g_ypart[gg][bbase + b][o];
            out[(bbase + b) * D_OUT + o] = s;
        }
    }
}

extern "C" void kernel_launch(void* const* d_in, const int* in_sizes, int n_in,
                              void* d_out, int out_size) {
    (void)in_sizes; (void)n_in; (void)out_size;
    cudaFuncSetAttribute(nef_kernel, cudaFuncAttributeMaxDynamicSharedMemorySize,
                         SMEM_BYTES);
    nef_kernel<<<NCTAS, THREADS, SMEM_BYTES>>>(
        (const float*)d_in[0],   // seq
        (const float*)d_in[1],   // encoders
        (const float*)d_in[2],   // bias
        (const float*)d_in[3],   // gain
        (const float*)d_in[4],   // state_decoders
        (const float*)d_in[5],   // decoders
        (float*)d_out);
}

// round 10
// speedup vs baseline: 1.2032x; 1.2032x over previous
#include <cuda_runtime.h>
#include <cuda_bf16.h>
#include <cstdint>

// -------- problem constants --------
#define BB      512
#define TT      256
#define D_IN    64
#define D_STATE 64
#define NN      2048
#define D_OUT   10
#define KAUG    128

// -------- decomposition: 16 neuron-groups x 8 batch-groups = 128 CTAs ----
#define NG      16
#define BG      8
#define NT      128     // neurons per CTA (GEMM1 N, GEMM2 K)
#define BT      64      // batch rows per CTA (M)
#define NCTAS   128
#define THREADS 512

// -------- SMEM: bf16 row-major, stride 136 (68 words = 4 mod 32 -> CF) ----
#define KS      136
#define KSW     68
#define XA_HI   0
#define XA_LO   (XA_HI  + BT * KS)
#define E_HI    (XA_LO  + BT * KS)
#define E_LO    (E_HI   + NT * KS)
#define SDT_HI  (E_LO   + NT * KS)
#define SDT_LO  (SDT_HI + D_STATE * KS)
#define A2_HI   (SDT_LO + D_STATE * KS)
#define A2_LO   (A2_HI  + BT * KS)
#define SMEM_ELEMS (A2_LO + BT * KS)
#define SMEM_BYTES (SMEM_ELEMS * 2)

// -------- global scratch (static; no allocation) --------
// Per-timestep accumulated state: REDG targets. Pre-zeroed each launch.
__device__ float g_s[TT][BB][D_STATE];          // 33.5 MB
__device__ float g_ypart[NG][BB][D_OUT];

// per-bi barriers (padded); gen monotonic across graph replays
__device__ unsigned g_cntb[BG * 32];
__device__ volatile unsigned g_genb[BG * 32];

__device__ __forceinline__ void gsync_bi(int bi) {
    __syncthreads();
    if (threadIdx.x == 0) {
        __threadfence();
        unsigned gen = g_genb[bi * 32];            // read BEFORE arriving
        unsigned prev = atomicAdd(&g_cntb[bi * 32], 1);
        if (prev == NG - 1) {
            g_cntb[bi * 32] = 0;
            __threadfence();
            g_genb[bi * 32] = gen + 1;
        } else {
            while (g_genb[bi * 32] == gen) { }
            __threadfence();
        }
    }
    __syncthreads();
}

// -------- warp-level bf16 MMA (sm_80+ baseline PTX; no arch-a gating) -----
__device__ __forceinline__ void mma_bf16(float* c, uint32_t a0, uint32_t a1,
                                         uint32_t a2, uint32_t a3,
                                         uint32_t b0, uint32_t b1) {
    asm volatile(
        "mma.sync.aligned.m16n8k16.row.col.f32.bf16.bf16.f32 "
        "{%0,%1,%2,%3}, {%4,%5,%6,%7}, {%8,%9}, {%0,%1,%2,%3};"
        : "+f"(c[0]), "+f"(c[1]), "+f"(c[2]), "+f"(c[3])
        : "r"(a0), "r"(a1), "r"(a2), "r"(a3), "r"(b0), "r"(b1));
}

// 3-pass split GEMM, 16x32 warp tile, K=128 (R5-proven load pattern).
// passes: (Ah,Bh) + (Al,Bh) + (Ah,Bl)
__device__ __forceinline__ void gemm3(const uint32_t* __restrict__ Ah,
                                      const uint32_t* __restrict__ Al,
                                      const uint32_t* __restrict__ Bh,
                                      const uint32_t* __restrict__ Bl,
                                      int m0, int n0, int g, int t4,
                                      float acc[4][4]) {
#pragma unroll
    for (int pass = 0; pass < 3; pass++) {
        const uint32_t* A = (pass == 1) ? Al : Ah;
        const uint32_t* B = (pass == 2) ? Bl : Bh;
#pragma unroll
        for (int ks = 0; ks < 8; ks++) {
            const int kw = ks * 8 + t4;            // word index: k0/2 + t
            const int r = m0 + g;
            uint32_t a0 = A[r * KSW + kw];
            uint32_t a1 = A[(r + 8) * KSW + kw];
            uint32_t a2 = A[r * KSW + kw + 4];
            uint32_t a3 = A[(r + 8) * KSW + kw + 4];
#pragma unroll
            for (int ns = 0; ns < 4; ns++) {
                const int c = n0 + 8 * ns + g;
                uint32_t b0 = B[c * KSW + kw];
                uint32_t b1 = B[c * KSW + kw + 4];
                mma_bf16(acc[ns], a0, a1, a2, a3, b0, b1);
            }
        }
    }
}

// split two floats into bf16 hi/lo pairs and store packed (k-pair granularity)
__device__ __forceinline__ void split_pair_store(__nv_bfloat16* bh, __nv_bfloat16* bl,
                                                 int row, int kpair, float x, float y) {
    __nv_bfloat162 h, l;
    h.x = __float2bfloat16(x);
    h.y = __float2bfloat16(y);
    l.x = __float2bfloat16(x - __bfloat162float(h.x));
    l.y = __float2bfloat16(y - __bfloat162float(h.y));
    *(__nv_bfloat162*)(bh + row * KS + kpair * 2) = h;
    *(__nv_bfloat162*)(bl + row * KS + kpair * 2) = l;
}

__global__ void __launch_bounds__(THREADS, 1)
nef_kernel(const float* __restrict__ seq,     // [B][T][D_IN]
           const float* __restrict__ enc,     // [NN][KAUG]
           const float* __restrict__ bias,    // [NN]
           const float* __restrict__ gain,    // [NN]
           const float* __restrict__ sdec,    // [NN][D_STATE]
           const float* __restrict__ dec,     // [NN][D_OUT]
           float* __restrict__ out)           // [B][D_OUT]
{
    extern __shared__ __nv_bfloat16 smem[];
    __nv_bfloat16* XAh = smem + XA_HI;
    __nv_bfloat16* XAl = smem + XA_LO;
    __nv_bfloat16* Eh  = smem + E_HI;
    __nv_bfloat16* El  = smem + E_LO;
    __nv_bfloat16* SDh = smem + SDT_HI;
    __nv_bfloat16* SDl = smem + SDT_LO;
    __nv_bfloat16* A2h = smem + A2_HI;
    __nv_bfloat16* A2l = smem + A2_LO;

    const uint32_t* XAh32 = (const uint32_t*)XAh;
    const uint32_t* XAl32 = (const uint32_t*)XAl;
    const uint32_t* Eh32  = (const uint32_t*)Eh;
    const uint32_t* El32  = (const uint32_t*)El;
    const uint32_t* SDh32 = (const uint32_t*)SDh;
    const uint32_t* SDl32 = (const uint32_t*)SDl;
    const uint32_t* A2h32 = (const uint32_t*)A2h;
    const uint32_t* A2l32 = (const uint32_t*)A2l;

    const int tid  = threadIdx.x;
    const int wid  = tid >> 5;
    const int lane = tid & 31;
    const int g    = lane >> 2;          // groupID
    const int t4   = lane & 3;           // thread-in-group
    const int ni   = blockIdx.x & (NG - 1);
    const int bi   = blockIdx.x >> 4;
    const int nbase = ni * NT;
    const int bbase = bi * BT;

    // GEMM1 warp tile (16x32): m0a in {0,16,32,48}, n0a in {0,32,64,96}
    const int m0a = 16 * (wid & 3);
    const int n0a = 32 * (wid >> 2);

    // ---- one-time weight staging (bf16 hi/lo) ----
    for (int i = tid; i < NT * (KAUG / 2); i += THREADS) {
        int n = i >> 6, p = i & 63;
        float2 v = *(const float2*)&enc[(nbase + n) * KAUG + 2 * p];
        split_pair_store(Eh, El, n, p, v.x, v.y);
    }
    for (int i = tid; i < D_STATE * (NT / 2); i += THREADS) {
        int d = i >> 6, p = i & 63;
        float x = sdec[(nbase + 2 * p) * D_STATE + d];
        float y = sdec[(nbase + 2 * p + 1) * D_STATE + d];
        split_pair_store(SDh, SDl, d, p, x, y);
    }
    // per-thread gain/bias for epilogue1 (columns n0a + 8ns + 2t4 (+1))
    float gj[4][2], bj[4][2];
#pragma unroll
    for (int ns = 0; ns < 4; ns++) {
        int n = nbase + n0a + 8 * ns + 2 * t4;
        gj[ns][0] = gain[n];     gj[ns][1] = gain[n + 1];
        bj[ns][0] = bias[n];     bj[ns][1] = bias[n + 1];
    }

    // ---- zero this bi-group's slice of g_s (bi-local coverage) ----
    // CTA (ni,bi) zeroes t in [ni*16, ni*16+16) for rows [bbase, bbase+64)
    {
        float4 z4 = make_float4(0.f, 0.f, 0.f, 0.f);
        for (int i = tid; i < 16 * BT * 16; i += THREADS) {   // 16384 float4
            int t  = ni * 16 + (i >> 10);
            int r  = (i >> 4) & 63;
            int dq = i & 15;
            *(float4*)&g_s[t][bbase + r][dq * 4] = z4;
        }
    }

    // ---- initial XA = [u(0) | 0] ----
    for (int i = tid; i < BT * (D_IN / 2); i += THREADS) {
        int r = i >> 5, p = i & 31;
        float2 v = *(const float2*)&seq[((size_t)(bbase + r) * TT) * D_IN + 2 * p];
        split_pair_store(XAh, XAl, r, p, v.x, v.y);
    }
    for (int i = tid; i < BT * (D_STATE / 2); i += THREADS) {
        int r = i >> 5, p = i & 31;
        split_pair_store(XAh, XAl, r, 32 + p, 0.f, 0.f);
    }
    gsync_bi(bi);   // g_s slice zeroed across the bi-group before any REDs

    for (int t = 0; t < TT; t++) {
        // ======== GEMM1: a = XA @ E^T (16 warps, 16x32 tiles) ========
        float acc[4][4];
#pragma unroll
        for (int ns = 0; ns < 4; ns++)
#pragma unroll
            for (int q = 0; q < 4; q++) acc[ns][q] = 0.f;

        gemm3(XAh32, XAl32, Eh32, El32, m0a, n0a, g, t4, acc);

        // ======== epilogue 1: act = |gain*v + bias| -> A2 hi/lo ========
#pragma unroll
        for (int ns = 0; ns < 4; ns++) {
            float v0 = fabsf(fmaf(gj[ns][0], acc[ns][0], bj[ns][0]));
            float v1 = fabsf(fmaf(gj[ns][1], acc[ns][1], bj[ns][1]));
            float v2 = fabsf(fmaf(gj[ns][0], acc[ns][2], bj[ns][0]));
            float v3 = fabsf(fmaf(gj[ns][1], acc[ns][3], bj[ns][1]));
            int r0 = m0a + g;
            int kp = (n0a + 8 * ns) / 2 + t4;
            split_pair_store(A2h, A2l, r0,     kp, v0, v1);
            split_pair_store(A2h, A2l, r0 + 8, kp, v2, v3);
        }

        if (t == TT - 1) break;

        __syncthreads();   // A2 visible to GEMM2 warps

        if (wid < 8) {
            // ======== GEMM2: s_part = a @ SD (warps 0-7, 16x32 tiles) ====
            const int m0b = 16 * (wid & 3);
            const int d0b = 32 * (wid >> 2);
            float acc2[4][4];
#pragma unroll
            for (int ns = 0; ns < 4; ns++)
#pragma unroll
                for (int q = 0; q < 4; q++) acc2[ns][q] = 0.f;

            gemm3(A2h32, A2l32, SDh32, SDl32, m0b, d0b, g, t4, acc2);

            // epilogue 2: REDG-accumulate state into per-timestep buffer
#pragma unroll
            for (int ns = 0; ns < 4; ns++) {
                int r0 = m0b + g;
                int d  = d0b + 8 * ns + 2 * t4;
                atomicAdd(&g_s[t][bbase + r0][d],         acc2[ns][0]);
                atomicAdd(&g_s[t][bbase + r0][d + 1],     acc2[ns][1]);
                atomicAdd(&g_s[t][bbase + r0 + 8][d],     acc2[ns][2]);
                atomicAdd(&g_s[t][bbase + r0 + 8][d + 1], acc2[ns][3]);
            }
        } else {
            // ---- concurrent prefetch: u(t+1) -> XA u-part ----
            for (int i = tid - 256; i < BT * (D_IN / 2); i += 256) {
                int r = i >> 5, p = i & 31;
                float2 v = *(const float2*)&seq[((size_t)(bbase + r) * TT + t + 1) * D_IN + 2 * p];
                split_pair_store(XAh, XAl, r, p, v.x, v.y);
            }
        }

        gsync_bi(bi);   // all 16 ni-sharers' REDs into g_s[t] are visible

        // ---- state fill: read accumulated s(t) (16 KB, L2-hot) -> XA ----
#pragma unroll
        for (int j = 0; j < 2; j++) {
            int item = tid + THREADS * j;        // 0..1023
            int r  = item >> 4;                  // 0..63
            int dq = item & 15;                  // float4 block within d
            float4 s = __ldcg((const float4*)&g_s[t][bbase + r][dq * 4]);
            split_pair_store(XAh, XAl, r, 32 + 2 * dq,     s.x, s.y);
            split_pair_store(XAh, XAl, r, 32 + 2 * dq + 1, s.z, s.w);
        }
        __syncthreads();
    }

    // ======== final decode: y = a @ dec ========
    __syncthreads();
    for (int idx = tid; idx < BT * D_OUT; idx += THREADS) {
        int b = idx / D_OUT, o = idx - b * D_OUT;
        float s = 0.f;
#pragma unroll 4
        for (int n = 0; n < NT; n++) {
            float a = __bfloat162float(A2h[b * KS + n]) + __bfloat162float(A2l[b * KS + n]);
            s += a * dec[(nbase + n) * D_OUT + o];
        }
        g_ypart[ni][bbase + b][o] = s;
    }
    gsync_bi(bi);

    if (ni == 0) {
        for (int idx = tid; idx < BT * D_OUT; idx += THREADS) {
            int b = idx / D_OUT, o = idx - b * D_OUT;
            float s = 0.f;
#pragma unroll
            for (int gg = 0; gg < NG; gg++)
                s += g_ypart[gg][bbase + b][o];
            out[(bbase + b) * D_OUT + o] = s;
        }
    }
}

extern "C" void kernel_launch(void* const* d_in, const int* in_sizes, int n_in,
                              void* d_out, int out_size) {
    (void)in_sizes; (void)n_in; (void)out_size;
    cudaFuncSetAttribute(nef_kernel, cudaFuncAttributeMaxDynamicSharedMemorySize,
                         SMEM_BYTES);
    nef_kernel<<<NCTAS, THREADS, SMEM_BYTES>>>(
        (const float*)d_in[0],   // seq
        (const float*)d_in[1],   // encoders
        (const float*)d_in[2],   // bias
        (const float*)d_in[3],   // gain
        (const float*)d_in[4],   // state_decoders
        (const float*)d_in[5],   // decoders
        (float*)d_out);
}

// round 11
// speedup vs baseline: 1.3372x; 1.1114x over previous
#include <cuda_runtime.h>
#include <cuda_bf16.h>
#include <cstdint>

// -------- problem constants --------
#define BB      512
#define TT      256
#define D_IN    64
#define D_STATE 64
#define NN      2048
#define D_OUT   10
#define KAUG    128

// -------- decomposition: 16 neuron-groups x 8 batch-groups = 128 CTAs ----
#define NG      16
#define BG      8
#define NT      128     // neurons per CTA (GEMM1 N, GEMM2 K)
#define BT      64      // batch rows per CTA (M)
#define NCTAS   128
#define THREADS 512

// -------- SMEM: bf16 row-major, stride 136 (68 words = 4 mod 32 -> CF) ----
#define KS      136
#define KSW     68
#define XA_HI   0
#define XA_LO   (XA_HI  + BT * KS)
#define E_HI    (XA_LO  + BT * KS)
#define E_LO    (E_HI   + NT * KS)
#define SDT_HI  (E_LO   + NT * KS)
#define SDT_LO  (SDT_HI + D_STATE * KS)
#define A2_HI   (SDT_LO + D_STATE * KS)
#define A2_LO   (A2_HI  + BT * KS)
#define SMEM_ELEMS (A2_LO + BT * KS)
#define SMEM_BYTES (SMEM_ELEMS * 2)

// -------- global scratch (static; no allocation) --------
// Per-timestep accumulated state: REDG targets. Zeroed per launch (bi-local).
__device__ float g_s[TT][BB][D_STATE];          // 33.5 MB
__device__ float g_ypart[NG][BB][D_OUT];

// per-bi barriers (padded); gen monotonic across graph replays
__device__ unsigned g_cntb[BG * 32];
__device__ volatile unsigned g_genb[BG * 32];

__device__ __forceinline__ void gsync_bi(int bi) {
    __syncthreads();
    if (threadIdx.x == 0) {
        __threadfence();
        unsigned gen = g_genb[bi * 32];            // read BEFORE arriving
        unsigned prev = atomicAdd(&g_cntb[bi * 32], 1);
        if (prev == NG - 1) {
            g_cntb[bi * 32] = 0;
            __threadfence();
            g_genb[bi * 32] = gen + 1;
        } else {
            while (g_genb[bi * 32] == gen) { }
            __threadfence();
        }
    }
    __syncthreads();
}

// -------- warp-level bf16 MMA (sm_80+ baseline PTX; no arch-a gating) -----
__device__ __forceinline__ void mma_bf16(float* c, uint32_t a0, uint32_t a1,
                                         uint32_t a2, uint32_t a3,
                                         uint32_t b0, uint32_t b1) {
    asm volatile(
        "mma.sync.aligned.m16n8k16.row.col.f32.bf16.bf16.f32 "
        "{%0,%1,%2,%3}, {%4,%5,%6,%7}, {%8,%9}, {%0,%1,%2,%3};"
        : "+f"(c[0]), "+f"(c[1]), "+f"(c[2]), "+f"(c[3])
        : "r"(a0), "r"(a1), "r"(a2), "r"(a3), "r"(b0), "r"(b1));
}

__device__ __forceinline__ void ldsm4(uint32_t addr, uint32_t* r) {
    asm volatile("ldmatrix.sync.aligned.m8n8.x4.shared.b16 {%0,%1,%2,%3}, [%4];"
        : "=r"(r[0]), "=r"(r[1]), "=r"(r[2]), "=r"(r[3]) : "r"(addr));
}

// 3 split passes (hh + lh + hl) for one n8 column group
__device__ __forceinline__ void mma3(float* c, const uint32_t* ah, const uint32_t* al,
                                     uint32_t bh0, uint32_t bh1,
                                     uint32_t bl0, uint32_t bl1) {
    mma_bf16(c, ah[0], ah[1], ah[2], ah[3], bh0, bh1);   // hi*hi
    mma_bf16(c, al[0], al[1], al[2], al[3], bh0, bh1);   // lo*hi
    mma_bf16(c, ah[0], ah[1], ah[2], ah[3], bl0, bl1);   // hi*lo
}

// 3-pass split GEMM, 16x32 warp tile, K=128, ldmatrix fragment loads.
// A=[rows][K] hi/lo, B=[cols][K] hi/lo, both KS-strided bf16 in SMEM.
__device__ __forceinline__ void gemm3(const __nv_bfloat16* Ah, const __nv_bfloat16* Al,
                                      const __nv_bfloat16* Bh, const __nv_bfloat16* Bl,
                                      int m0, int n0, int lane,
                                      float acc[4][4]) {
    const int rowA = m0 + (lane & 15);
    const int colA = (lane >> 4) << 3;
    const int rowB = n0 + ((lane >> 4) << 3) + (lane & 7);
    const int colB = ((lane >> 3) & 1) << 3;

    uint32_t aH  = (uint32_t)__cvta_generic_to_shared(Ah + rowA * KS + colA);
    uint32_t aL  = (uint32_t)__cvta_generic_to_shared(Al + rowA * KS + colA);
    uint32_t bH0 = (uint32_t)__cvta_generic_to_shared(Bh + rowB * KS + colB);
    uint32_t bL0 = (uint32_t)__cvta_generic_to_shared(Bl + rowB * KS + colB);
    const uint32_t nstep = 16u * KS * 2u;          // +16 B-rows (bytes)

#pragma unroll
    for (int ks = 0; ks < 8; ks++) {
        const uint32_t o = (uint32_t)ks * 32u;     // 16 bf16 = 32B along k
        uint32_t ah[4], al[4], bh0[4], bh1[4], bl0[4], bl1[4];
        ldsm4(aH + o, ah);
        ldsm4(aL + o, al);
        ldsm4(bH0 + o, bh0);
        ldsm4(bH0 + nstep + o, bh1);
        ldsm4(bL0 + o, bl0);
        ldsm4(bL0 + nstep + o, bl1);
        mma3(acc[0], ah, al, bh0[0], bh0[1], bl0[0], bl0[1]);   // ns=0
        mma3(acc[1], ah, al, bh0[2], bh0[3], bl0[2], bl0[3]);   // ns=1
        mma3(acc[2], ah, al, bh1[0], bh1[1], bl1[0], bl1[1]);   // ns=2
        mma3(acc[3], ah, al, bh1[2], bh1[3], bl1[2], bl1[3]);   // ns=3
    }
}

// split two floats into bf16 hi/lo pairs and store packed (k-pair granularity)
__device__ __forceinline__ void split_pair_store(__nv_bfloat16* bh, __nv_bfloat16* bl,
                                                 int row, int kpair, float x, float y) {
    __nv_bfloat162 h, l;
    h.x = __float2bfloat16(x);
    h.y = __float2bfloat16(y);
    l.x = __float2bfloat16(x - __bfloat162float(h.x));
    l.y = __float2bfloat16(y - __bfloat162float(h.y));
    *(__nv_bfloat162*)(bh + row * KS + kpair * 2) = h;
    *(__nv_bfloat162*)(bl + row * KS + kpair * 2) = l;
}

__global__ void __launch_bounds__(THREADS, 1)
nef_kernel(const float* __restrict__ seq,     // [B][T][D_IN]
           const float* __restrict__ enc,     // [NN][KAUG]
           const float* __restrict__ bias,    // [NN]
           const float* __restrict__ gain,    // [NN]
           const float* __restrict__ sdec,    // [NN][D_STATE]
           const float* __restrict__ dec,     // [NN][D_OUT]
           float* __restrict__ out)           // [B][D_OUT]
{
    extern __shared__ __nv_bfloat16 smem[];
    __nv_bfloat16* XAh = smem + XA_HI;
    __nv_bfloat16* XAl = smem + XA_LO;
    __nv_bfloat16* Eh  = smem + E_HI;
    __nv_bfloat16* El  = smem + E_LO;
    __nv_bfloat16* SDh = smem + SDT_HI;
    __nv_bfloat16* SDl = smem + SDT_LO;
    __nv_bfloat16* A2h = smem + A2_HI;
    __nv_bfloat16* A2l = smem + A2_LO;

    const int tid  = threadIdx.x;
    const int wid  = tid >> 5;
    const int lane = tid & 31;
    const int g    = lane >> 2;          // groupID
    const int t4   = lane & 3;           // thread-in-group
    const int ni   = blockIdx.x & (NG - 1);
    const int bi   = blockIdx.x >> 4;
    const int nbase = ni * NT;
    const int bbase = bi * BT;

    // GEMM1 warp tile (16x32): m0a in {0,16,32,48}, n0a in {0,32,64,96}
    const int m0a = 16 * (wid & 3);
    const int n0a = 32 * (wid >> 2);

    // ---- one-time weight staging (bf16 hi/lo) ----
    for (int i = tid; i < NT * (KAUG / 2); i += THREADS) {
        int n = i >> 6, p = i & 63;
        float2 v = *(const float2*)&enc[(nbase + n) * KAUG + 2 * p];
        split_pair_store(Eh, El, n, p, v.x, v.y);
    }
    for (int i = tid; i < D_STATE * (NT / 2); i += THREADS) {
        int d = i >> 6, p = i & 63;
        float x = sdec[(nbase + 2 * p) * D_STATE + d];
        float y = sdec[(nbase + 2 * p + 1) * D_STATE + d];
        split_pair_store(SDh, SDl, d, p, x, y);
    }
    // per-thread gain/bias for epilogue1 (columns n0a + 8ns + 2t4 (+1))
    float gj[4][2], bj[4][2];
#pragma unroll
    for (int ns = 0; ns < 4; ns++) {
        int n = nbase + n0a + 8 * ns + 2 * t4;
        gj[ns][0] = gain[n];     gj[ns][1] = gain[n + 1];
        bj[ns][0] = bias[n];     bj[ns][1] = bias[n + 1];
    }

    // ---- zero this bi-group's slice of g_s (bi-local coverage) ----
    // CTA (ni,bi) zeroes t in [ni*16, ni*16+16) for rows [bbase, bbase+64)
    {
        float4 z4 = make_float4(0.f, 0.f, 0.f, 0.f);
        for (int i = tid; i < 16 * BT * 16; i += THREADS) {   // 16384 float4
            int t  = ni * 16 + (i >> 10);
            int r  = (i >> 4) & 63;
            int dq = i & 15;
            *(float4*)&g_s[t][bbase + r][dq * 4] = z4;
        }
    }

    // ---- initial XA = [u(0) | 0] ----
    for (int i = tid; i < BT * (D_IN / 2); i += THREADS) {
        int r = i >> 5, p = i & 31;
        float2 v = *(const float2*)&seq[((size_t)(bbase + r) * TT) * D_IN + 2 * p];
        split_pair_store(XAh, XAl, r, p, v.x, v.y);
    }
    for (int i = tid; i < BT * (D_STATE / 2); i += THREADS) {
        int r = i >> 5, p = i & 31;
        split_pair_store(XAh, XAl, r, 32 + p, 0.f, 0.f);
    }
    gsync_bi(bi);   // g_s slice zeroed across the bi-group before any REDs

    for (int t = 0; t < TT; t++) {
        // ======== GEMM1: a = XA @ E^T (16 warps, 16x32 tiles) ========
        float acc[4][4];
#pragma unroll
        for (int ns = 0; ns < 4; ns++)
#pragma unroll
            for (int q = 0; q < 4; q++) acc[ns][q] = 0.f;

        gemm3(XAh, XAl, Eh, El, m0a, n0a, lane, acc);

        // ======== epilogue 1: act = |gain*v + bias| -> A2 hi/lo ========
#pragma unroll
        for (int ns = 0; ns < 4; ns++) {
            float v0 = fabsf(fmaf(gj[ns][0], acc[ns][0], bj[ns][0]));
            float v1 = fabsf(fmaf(gj[ns][1], acc[ns][1], bj[ns][1]));
            float v2 = fabsf(fmaf(gj[ns][0], acc[ns][2], bj[ns][0]));
            float v3 = fabsf(fmaf(gj[ns][1], acc[ns][3], bj[ns][1]));
            int r0 = m0a + g;
            int kp = (n0a + 8 * ns) / 2 + t4;
            split_pair_store(A2h, A2l, r0,     kp, v0, v1);
            split_pair_store(A2h, A2l, r0 + 8, kp, v2, v3);
        }

        if (t == TT - 1) break;

        __syncthreads();   // A2 visible to GEMM2 warps

        if (wid < 8) {
            // ======== GEMM2: s_part = a @ SD (warps 0-7, 16x32 tiles) ====
            const int m0b = 16 * (wid & 3);
            const int d0b = 32 * (wid >> 2);
            float acc2[4][4];
#pragma unroll
            for (int ns = 0; ns < 4; ns++)
#pragma unroll
                for (int q = 0; q < 4; q++) acc2[ns][q] = 0.f;

            gemm3(A2h, A2l, SDh, SDl, m0b, d0b, lane, acc2);

            // epilogue 2: REDG-accumulate state into per-timestep buffer
#pragma unroll
            for (int ns = 0; ns < 4; ns++) {
                int r0 = m0b + g;
                int d  = d0b + 8 * ns + 2 * t4;
                atomicAdd(&g_s[t][bbase + r0][d],         acc2[ns][0]);
                atomicAdd(&g_s[t][bbase + r0][d + 1],     acc2[ns][1]);
                atomicAdd(&g_s[t][bbase + r0 + 8][d],     acc2[ns][2]);
                atomicAdd(&g_s[t][bbase + r0 + 8][d + 1], acc2[ns][3]);
            }
        } else {
            // ---- concurrent prefetch: u(t+1) -> XA u-part ----
            for (int i = tid - 256; i < BT * (D_IN / 2); i += 256) {
                int r = i >> 5, p = i & 31;
                float2 v = *(const float2*)&seq[((size_t)(bbase + r) * TT + t + 1) * D_IN + 2 * p];
                split_pair_store(XAh, XAl, r, p, v.x, v.y);
            }
        }

        gsync_bi(bi);   // all 16 ni-sharers' REDs into g_s[t] are visible

        // ---- state fill: read accumulated s(t) (16 KB, L2-hot) -> XA ----
#pragma unroll
        for (int j = 0; j < 2; j++) {
            int item = tid + THREADS * j;        // 0..1023
            int r  = item >> 4;                  // 0..63
            int dq = item & 15;                  // float4 block within d
            float4 s = __ldcg((const float4*)&g_s[t][bbase + r][dq * 4]);
            split_pair_store(XAh, XAl, r, 32 + 2 * dq,     s.x, s.y);
            split_pair_store(XAh, XAl, r, 32 + 2 * dq + 1, s.z, s.w);
        }
        __syncthreads();
    }

    // ======== final decode: y = a @ dec ========
    __syncthreads();
    for (int idx = tid; idx < BT * D_OUT; idx += THREADS) {
        int b = idx / D_OUT, o = idx - b * D_OUT;
        float s = 0.f;
#pragma unroll 4
        for (int n = 0; n < NT; n++) {
            float a = __bfloat162float(A2h[b * KS + n]) + __bfloat162float(A2l[b * KS + n]);
            s += a * dec[(nbase + n) * D_OUT + o];
        }
        g_ypart[ni][bbase + b][o] = s;
    }
    gsync_bi(bi);

    if (ni == 0) {
        for (int idx = tid; idx < BT * D_OUT; idx += THREADS) {
            int b = idx / D_OUT, o = idx - b * D_OUT;
            float s = 0.f;
#pragma unroll
            for (int gg = 0; gg < NG; gg++)
                s += g_ypart[gg][bbase + b][o];
            out[(bbase + b) * D_OUT + o] = s;
        }
    }
}

extern "C" void kernel_launch(void* const* d_in, const int* in_sizes, int n_in,
                              void* d_out, int out_size) {
    (void)in_sizes; (void)n_in; (void)out_size;
    cudaFuncSetAttribute(nef_kernel, cudaFuncAttributeMaxDynamicSharedMemorySize,
                         SMEM_BYTES);
    nef_kernel<<<NCTAS, THREADS, SMEM_BYTES>>>(
        (const float*)d_in[0],   // seq
        (const float*)d_in[1],   // encoders
        (const float*)d_in[2],   // bias
        (const float*)d_in[3],   // gain
        (const float*)d_in[4],   // state_decoders
        (const float*)d_in[5],   // decoders
        (float*)d_out);
}